// round 12
// baseline (speedup 1.0000x reference)
#include <cuda_runtime.h>
#include <cuda_fp16.h>
#include <cstdint>

// ============================================================================
// Fused ConvTranspose3d(32->64,k=5,s=2,p=2) + MaxPool(2)+MaxPool(3) + ch-sum
// via mma.sync FP16 implicit GEMM (m16n8k16, fp32 accum), ldmatrix loads.
//
// R12: 6-deep B ring, 2 taps per round, ONE barrier per round (63 rounds vs
// 250 barriers before). Prefetch issued 2 rounds ahead (slot = t mod 6).
// Tap/class tables live in the 16B tail padding of the 80B xs rows; part
// stride 97 -> smem 113152 B, 2 CTAs/SM.
//
// CTA = 1 od x 2 oh x 5 ow cells (grid 2x25x16 = 800, 192 thr, 6 warps).
// Per parity class (pd,ph,pw): GEMM M=288 (ri3 x rhi6 x j16, j=w innermost
// -> ldmatrix matrices read 8 consecutive 80B rows: conflict-free), N=64,
// K=32/tap. Epilogue per class: 3 stages by ri -> part[oc][97] -> cell max.
// ============================================================================

typedef unsigned int uint;

#define THREADS 192
#define PS 97
#define B_OFF    57600           // xs: 720 rows x 80B (data 64B + 16B pad)
#define PART_OFF 88320           // B ring: 6 x 5120B
#define SMEM_BYTES 113152        // part: 64*97*4 = 24832B

__device__ __align__(16) __half g_wtH[125 * 64 * 32];   // [tap][oc][ic32]

__global__ void wt_prep_kernel(const float* __restrict__ w) {
    int idx = blockIdx.x * blockDim.x + threadIdx.x;
    if (idx >= 125 * 64 * 32) return;
    int ic  = idx & 31;
    int oc  = (idx >> 5) & 63;
    int tap = idx >> 11;
    g_wtH[(tap * 64 + oc) * 32 + ic] =
        __float2half_rn(w[(ic * 64 + oc) * 125 + tap]);
}

__device__ __forceinline__ void cpa16(char* s, const void* g) {
    uint sa = (uint)__cvta_generic_to_shared(s);
    asm volatile("cp.async.cg.shared.global [%0], [%1], 16;" :: "r"(sa), "l"(g));
}
__device__ __forceinline__ void cp_commit() {
    asm volatile("cp.async.commit_group;");
}
__device__ __forceinline__ void cp_wait1() {
    asm volatile("cp.async.wait_group 1;" ::: "memory");
}
__device__ __forceinline__ void ldm_x4(uint* r, uint addr) {
    asm volatile("ldmatrix.sync.aligned.m8n8.x4.shared.b16 {%0,%1,%2,%3}, [%4];"
                 : "=r"(r[0]), "=r"(r[1]), "=r"(r[2]), "=r"(r[3]) : "r"(addr));
}
__device__ __forceinline__ void mma_f16(float* c, const uint* a, const uint* b) {
    asm volatile(
        "mma.sync.aligned.m16n8k16.row.col.f32.f16.f16.f32 "
        "{%0,%1,%2,%3}, {%4,%5,%6,%7}, {%8,%9}, {%0,%1,%2,%3};"
        : "+f"(c[0]), "+f"(c[1]), "+f"(c[2]), "+f"(c[3])
        : "r"(a[0]), "r"(a[1]), "r"(a[2]), "r"(a[3]), "r"(b[0]), "r"(b[1]));
}

extern __shared__ char smem_raw[];

__global__ void __launch_bounds__(THREADS, 2)
fused_kernel(const float* __restrict__ x,
             const float* __restrict__ bias,
             float* __restrict__ out) {
    char*  xsb  = smem_raw;                     // x rows, 80B stride
    char*  btb  = smem_raw + B_OFF;             // 6-slot B ring
    float* part = (float*)(smem_raw + PART_OFF);

    const int whp = blockIdx.x;                 // w half-line (5 ow cells)
    const int odp = blockIdx.y / 5;
    const int ohp = blockIdx.y % 5;
    const int b   = blockIdx.z;
    const int tid  = threadIdx.x;
    const int wid  = tid >> 5;
    const int lane = tid & 31;
    const int lane7 = lane & 7;
    const int lm4 = lane & 3, ld4 = lane >> 2;

    const uint xs_u  = (uint)__cvta_generic_to_shared(xsb);
    const uint bt_u0 = (uint)__cvta_generic_to_shared(btb);

    // ---- tables in xs row padding: tap@(row*80+64), abase@(+68),
    //      class-end table at rows 130..137 (+64) ----
    if (tid == 0) {
        int t = 0;
        for (int pd = 0; pd < 2; pd++)
            for (int ph = 0; ph < 2; ph++)
                for (int pw = 0; pw < 2; pw++)
                    for (int jd = 0; jd < 3 - pd; jd++)
                        for (int jh = 0; jh < 3 - ph; jh++)
                            for (int jw = 0; jw < 3 - pw; jw++) {
                                int kd = pd + 2 * jd, kh = ph + 2 * jh,
                                    kw = pw + 2 * jw;
                                *(int*)(xsb + t * 80 + 64) =
                                    (kd * 5 + kh) * 5 + kw;
                                *(int*)(xsb + t * 80 + 68) =
                                    ((2 - jd) * 144 + (2 - jh) * 18 +
                                     (2 - jw)) * 80;
                                t++;
                            }
        const int ce[8] = {27, 45, 63, 75, 93, 105, 117, 999};
        for (int i = 0; i < 8; i++)
            *(int*)(xsb + (130 + i) * 80 + 64) = ce[i];
    }
    __syncthreads();    // tables visible

    // ---- preload B for rounds 0,1 (taps 0..3), one group per round ----
    #pragma unroll
    for (int g = 0; g < 2; g++) {
        #pragma unroll
        for (int dt = 0; dt < 2; dt++) {
            int pf = 2 * g + dt;
            int tap = *(const int*)(xsb + pf * 80 + 64);
            const __half* src = g_wtH + tap * 2048;
            char* dst = btb + pf * 5120;
            for (int q = tid; q < 256; q += THREADS)
                cpa16(dst + (q >> 2) * 80 + (q & 3) * 16,
                      src + (q >> 2) * 32 + (q & 3) * 8);
        }
        cp_commit();
    }

    // ---- x patch fill: row R = (ild*8 + ilh)*18 + ilw, 32 ic halfs ----
    {
        const int d0 = 3 * odp - 1, h0 = 6 * ohp - 1, w0 = 15 * whp - 1;
        for (int icp = 0; icp < 16; icp++) {
            const float* xpl = x + (size_t)(b * 32 + 2 * icp) * 16384;
            for (int R = tid; R < 720; R += THREADS) {
                int ild = R / 144, rem = R % 144;
                int ilh = rem / 18, ilw = rem % 18;
                int id = d0 + ild, ih = h0 + ilh, iw = w0 + ilw;
                float v0 = 0.0f, v1 = 0.0f;
                if (id >= 0 && ih >= 0 && iw >= 0) {
                    const float* p = xpl + (id * 32 + ih) * 32 + iw;
                    v0 = p[0];
                    v1 = p[16384];
                }
                *(__half2*)(xsb + R * 80 + icp * 4) =
                    __floats2half2_rn(v0, v1);
            }
        }
    }
    // visibility of xs covered by round 0's barrier

    // ---- per-lane / per-warp address constants ----
    const uint laneA = (uint)(lane7 * 80 + ((lane >> 3) & 1) * 640 +
                              (lane >> 4) * 16);
    const uint laneB = (uint)(((lane >> 4) * 8 + lane7) * 80 +
                              ((lane >> 3) & 1) * 16);
    const uint wA = (uint)((wid >> 1) * 11520 + (wid & 1) * 4320);

    float regAll[4] = {-3.4e38f, -3.4e38f, -3.4e38f, -3.4e38f};
    float C[3][8][4];
    #pragma unroll
    for (int mt = 0; mt < 3; mt++)
        #pragma unroll
        for (int nt = 0; nt < 8; nt++)
            #pragma unroll
            for (int e = 0; e < 4; e++)
                C[mt][nt][e] = 0.0f;

    int ce_idx = 0;
    int next_end = 27;

    // ================= main loop: 63 rounds of 2 taps =================
    #pragma unroll 1
    for (int r = 0; r < 63; r++) {
        const int t0 = 2 * r;
        cp_wait1();          // own copies for taps t0, t0+1 arrived
        __syncthreads();     // all copies visible; prior round's reads done

        // prefetch round r+2's taps into slots (t0+4)%6, (t0+5)%6
        #pragma unroll
        for (int dt = 4; dt < 6; dt++) {
            int pf = t0 + dt;
            if (pf < 125) {
                int tap = *(const int*)(xsb + pf * 80 + 64);
                const __half* src = g_wtH + tap * 2048;
                char* dst = btb + (pf % 6) * 5120;
                for (int q = tid; q < 256; q += THREADS)
                    cpa16(dst + (q >> 2) * 80 + (q & 3) * 16,
                          src + (q >> 2) * 32 + (q & 3) * 8);
            }
        }
        cp_commit();

        // compute taps t0, t0+1
        #pragma unroll 1
        for (int dt = 0; dt < 2; dt++) {
            const int t = t0 + dt;
            if (t >= 125) break;

            if (t == next_end) {
                // ---- class epilogue: 3 stages by ri ----
                #pragma unroll 1
                for (int s = 0; s < 3; s++) {
                    __syncthreads();
                    if ((wid >> 1) == s) {
                        const int rb = 3 * (wid & 1);
                        #pragma unroll
                        for (int mt = 0; mt < 3; mt++)
                            #pragma unroll
                            for (int nt = 0; nt < 8; nt++) {
                                int oc0 = nt * 8 + 2 * lm4;
                                int pos0 = (rb + mt) * 16 + ld4;
                                part[oc0 * PS + pos0]           = C[mt][nt][0];
                                part[(oc0 + 1) * PS + pos0]     = C[mt][nt][1];
                                part[oc0 * PS + pos0 + 8]       = C[mt][nt][2];
                                part[(oc0 + 1) * PS + pos0 + 8] = C[mt][nt][3];
                            }
                    }
                    __syncthreads();
                    {
                        const int oc = tid & 63, slot = tid >> 6;
                        const float* pr = part + oc * PS;
                        #pragma unroll
                        for (int k = 0; k < 4; k++) {
                            int cc = slot + 3 * k;
                            if (cc < 10) {
                                int chh = (cc >= 5) ? 1 : 0;
                                int cw = cc - 5 * chh;
                                const float* pb = pr + chh * 48 + 3 * cw;
                                float m = regAll[k];
                                #pragma unroll
                                for (int u = 0; u < 3; u++)
                                    #pragma unroll
                                    for (int v = 0; v < 3; v++)
                                        m = fmaxf(m, pb[u * 16 + v]);
                                regAll[k] = m;
                            }
                        }
                    }
                }
                #pragma unroll
                for (int mt = 0; mt < 3; mt++)
                    #pragma unroll
                    for (int nt = 0; nt < 8; nt++)
                        #pragma unroll
                        for (int e = 0; e < 4; e++)
                            C[mt][nt][e] = 0.0f;
                ce_idx++;
                next_end = *(const int*)(xsb + (130 + ce_idx) * 80 + 64);
            }

            const int abase = *(const int*)(xsb + t * 80 + 68);
            const uint bt_u = bt_u0 + (uint)((t % 6) * 5120) + laneB;
            const uint aa = xs_u + (uint)abase + wA + laneA;
            #pragma unroll
            for (int ks = 0; ks < 2; ks++) {
                uint bfr[8][2];
                #pragma unroll
                for (int q = 0; q < 4; q++) {
                    uint rr[4];
                    ldm_x4(rr, bt_u + (uint)(q * 1280 + ks * 32));
                    bfr[2 * q][0] = rr[0];  bfr[2 * q][1] = rr[1];
                    bfr[2 * q + 1][0] = rr[2]; bfr[2 * q + 1][1] = rr[3];
                }
                #pragma unroll
                for (int mt = 0; mt < 3; mt++) {
                    uint a[4];
                    ldm_x4(a, aa + (uint)(mt * 1440 + ks * 32));
                    #pragma unroll
                    for (int nt = 0; nt < 8; nt++)
                        mma_f16(C[mt][nt], a, bfr[nt]);
                }
            }
        }
    }

    // ---- final class (cls 7) epilogue ----
    #pragma unroll 1
    for (int s = 0; s < 3; s++) {
        __syncthreads();
        if ((wid >> 1) == s) {
            const int rb = 3 * (wid & 1);
            #pragma unroll
            for (int mt = 0; mt < 3; mt++)
                #pragma unroll
                for (int nt = 0; nt < 8; nt++) {
                    int oc0 = nt * 8 + 2 * lm4;
                    int pos0 = (rb + mt) * 16 + ld4;
                    part[oc0 * PS + pos0]           = C[mt][nt][0];
                    part[(oc0 + 1) * PS + pos0]     = C[mt][nt][1];
                    part[oc0 * PS + pos0 + 8]       = C[mt][nt][2];
                    part[(oc0 + 1) * PS + pos0 + 8] = C[mt][nt][3];
                }
        }
        __syncthreads();
        {
            const int oc = tid & 63, slot = tid >> 6;
            const float* pr = part + oc * PS;
            #pragma unroll
            for (int k = 0; k < 4; k++) {
                int cc = slot + 3 * k;
                if (cc < 10) {
                    int chh = (cc >= 5) ? 1 : 0;
                    int cw = cc - 5 * chh;
                    const float* pb = pr + chh * 48 + 3 * cw;
                    float m = regAll[k];
                    #pragma unroll
                    for (int u = 0; u < 3; u++)
                        #pragma unroll
                        for (int v = 0; v < 3; v++)
                            m = fmaxf(m, pb[u * 16 + v]);
                    regAll[k] = m;
                }
            }
        }
    }

    // ---- final: +bias, sum over oc per cell ----
    __syncthreads();
    float* red = part;    // [10][64]
    {
        const int oc = tid & 63, slot = tid >> 6;
        #pragma unroll
        for (int k = 0; k < 4; k++) {
            int cc = slot + 3 * k;
            if (cc < 10) red[cc * 64 + oc] = regAll[k] + bias[oc];
        }
    }
    __syncthreads();
    for (int cc = wid; cc < 10; cc += 6) {
        float v = red[cc * 64 + lane] + red[cc * 64 + 32 + lane];
        #pragma unroll
        for (int off = 16; off > 0; off >>= 1)
            v += __shfl_xor_sync(0xffffffffu, v, off);
        if (lane == 0) {
            int chh = (cc >= 5) ? 1 : 0;
            int cw = cc - 5 * chh;
            out[((b * 5 + odp) * 10 + 2 * ohp + chh) * 10 + 5 * whp + cw] = v;
        }
    }
}

// ---------------------------------------------------------------------------
extern "C" void kernel_launch(void* const* d_in, const int* in_sizes, int n_in,
                              void* d_out, int out_size) {
    const float* x    = (const float*)d_in[0];   // [16,32,16,32,32]
    const float* w    = (const float*)d_in[1];   // [32,64,5,5,5]
    const float* bias = (const float*)d_in[2];   // [64]
    float* out = (float*)d_out;                  // 8000

    wt_prep_kernel<<<(125 * 64 * 32 + 255) / 256, 256>>>(w);

    cudaFuncSetAttribute(fused_kernel,
                         cudaFuncAttributeMaxDynamicSharedMemorySize,
                         SMEM_BYTES);
    dim3 grid(2, 25, 16);   // (w half-line, odp*5+ohp, b)
    fused_kernel<<<grid, THREADS, SMEM_BYTES>>>(x, bias, out);
}

// round 13
// speedup vs baseline: 1.1689x; 1.1689x over previous
#include <cuda_runtime.h>
#include <cuda_fp16.h>
#include <cstdint>

// ============================================================================
// Fused ConvTranspose3d(32->64,k=5,s=2,p=2) + MaxPool(2)+MaxPool(3) + ch-sum
// via mma.sync FP16 implicit GEMM (m16n8k16, fp32 accum), ldmatrix loads.
//
// R13 = R11 compute body + single-barrier-per-tap multistage pipeline:
// 4-slot B ring, prefetch distance 2, one __syncthreads per tap (was 2).
// wait_group 1 + barrier publishes tap t and retires reads of the slot
// being overwritten (last read at tap t-2). Commit every iteration so the
// group carrying tap t is always retired by wait_group 1.
//
// CTA = 1 od x 2 oh x 5 ow cells (grid 2x25x16 = 800, 192 thr, 6 warps,
// 2 CTAs/SM). Per parity class: GEMM M=288 (ri3 x rhi6 x j16, j innermost
// -> ldmatrix reads 8 consecutive 80B rows: conflict-free), N=64, K=32/tap.
// Epilogue per class: 3 stages by ri -> part[oc][PS=101] -> cell max.
// ============================================================================

typedef unsigned int uint;

#define THREADS 192
#define PS 101
// smem byte offsets
#define B_OFF    57600           // xs: 720 rows x 80B
#define PART_OFF 78080           // B ring: 4 x 5120B = 20480
#define TL_OFF   103936          // part: 64*101*4 = 25856B
#define SMEM_BYTES 104960

__device__ __align__(16) __half g_wtH[125 * 64 * 32];   // [tap][oc][ic32]

// g_wtH[tap][oc][ic] <- fp16(w[ic][oc][kd][kh][kw])
__global__ void wt_prep_kernel(const float* __restrict__ w) {
    int idx = blockIdx.x * blockDim.x + threadIdx.x;
    if (idx >= 125 * 64 * 32) return;
    int ic  = idx & 31;
    int oc  = (idx >> 5) & 63;
    int tap = idx >> 11;
    g_wtH[(tap * 64 + oc) * 32 + ic] =
        __float2half_rn(w[(ic * 64 + oc) * 125 + tap]);
}

__device__ __forceinline__ void cpa16(char* s, const void* g) {
    uint sa = (uint)__cvta_generic_to_shared(s);
    asm volatile("cp.async.cg.shared.global [%0], [%1], 16;" :: "r"(sa), "l"(g));
}
__device__ __forceinline__ void cp_commit() {
    asm volatile("cp.async.commit_group;");
}
__device__ __forceinline__ void cp_wait1() {
    asm volatile("cp.async.wait_group 1;" ::: "memory");
}

__device__ __forceinline__ void ldm_x4(uint* r, uint addr) {
    asm volatile("ldmatrix.sync.aligned.m8n8.x4.shared.b16 {%0,%1,%2,%3}, [%4];"
                 : "=r"(r[0]), "=r"(r[1]), "=r"(r[2]), "=r"(r[3]) : "r"(addr));
}

__device__ __forceinline__ void mma_f16(float* c, const uint* a, const uint* b) {
    asm volatile(
        "mma.sync.aligned.m16n8k16.row.col.f32.f16.f16.f32 "
        "{%0,%1,%2,%3}, {%4,%5,%6,%7}, {%8,%9}, {%0,%1,%2,%3};"
        : "+f"(c[0]), "+f"(c[1]), "+f"(c[2]), "+f"(c[3])
        : "r"(a[0]), "r"(a[1]), "r"(a[2]), "r"(a[3]), "r"(b[0]), "r"(b[1]));
}

extern __shared__ char smem_raw[];

__global__ void __launch_bounds__(THREADS, 2)
fused_kernel(const float* __restrict__ x,
             const float* __restrict__ bias,
             float* __restrict__ out) {
    char*  xsb  = smem_raw;                     // x rows: R in [0,720), 80B
    char*  btb  = smem_raw + B_OFF;             // 4-slot B ring
    float* part = (float*)(smem_raw + PART_OFF);
    int* tl_tap   = (int*)(smem_raw + TL_OFF);
    int* tl_abase = tl_tap + 125;

    const int whp = blockIdx.x;                 // w half-line (5 ow cells)
    const int odp = blockIdx.y / 5;
    const int ohp = blockIdx.y % 5;
    const int b   = blockIdx.z;
    const int tid  = threadIdx.x;
    const int wid  = tid >> 5;
    const int lane = tid & 31;
    const int lane7 = lane & 7;
    const int lm4 = lane & 3, ld4 = lane >> 2;

    const uint xs_u  = (uint)__cvta_generic_to_shared(xsb);
    const uint bt_u0 = (uint)__cvta_generic_to_shared(btb);

    // ---- tap tables (thread 0): grouped by class (pd,ph,pw) ----
    if (tid == 0) {
        int t = 0;
        for (int pd = 0; pd < 2; pd++)
            for (int ph = 0; ph < 2; ph++)
                for (int pw = 0; pw < 2; pw++)
                    for (int jd = 0; jd < 3 - pd; jd++)
                        for (int jh = 0; jh < 3 - ph; jh++)
                            for (int jw = 0; jw < 3 - pw; jw++) {
                                int kd = pd + 2 * jd, kh = ph + 2 * jh,
                                    kw = pw + 2 * jw;
                                tl_tap[t] = (kd * 5 + kh) * 5 + kw;
                                tl_abase[t] =
                                    ((2 - jd) * 144 + (2 - jh) * 18 +
                                     (2 - jw)) * 80;
                                t++;
                            }
    }
    __syncthreads();    // tables visible (needed for prologue prefetch)

    // ---- prologue: preload B for taps 0 and 1 (separate commit groups) ----
    #pragma unroll
    for (int pf = 0; pf < 2; pf++) {
        const __half* src = g_wtH + tl_tap[pf] * 2048;
        char* dst = btb + pf * 5120;
        for (int q = tid; q < 256; q += THREADS)
            cpa16(dst + (q >> 2) * 80 + (q & 3) * 16,
                  src + (q >> 2) * 32 + (q & 3) * 8);
        cp_commit();
    }

    // ---- x patch fill: row R = (ild*8 + ilh)*18 + ilw, 32 ic halfs ----
    {
        const int d0 = 3 * odp - 1, h0 = 6 * ohp - 1, w0 = 15 * whp - 1;
        for (int icp = 0; icp < 16; icp++) {
            const float* xpl = x + (size_t)(b * 32 + 2 * icp) * 16384;
            for (int R = tid; R < 720; R += THREADS) {
                int ild = R / 144, rem = R % 144;
                int ilh = rem / 18, ilw = rem % 18;
                int id = d0 + ild, ih = h0 + ilh, iw = w0 + ilw;
                float v0 = 0.0f, v1 = 0.0f;
                if (id >= 0 && ih >= 0 && iw >= 0) {
                    const float* p = xpl + (id * 32 + ih) * 32 + iw;
                    v0 = p[0];
                    v1 = p[16384];
                }
                *(__half2*)(xsb + R * 80 + icp * 4) =
                    __floats2half2_rn(v0, v1);
            }
        }
    }
    // xs visibility covered by tap 0's barrier below

    // ---- per-lane / per-warp address constants ----
    const uint laneA = (uint)(lane7 * 80 + ((lane >> 3) & 1) * 640 +
                              (lane >> 4) * 16);
    const uint laneB = (uint)(((lane >> 4) * 8 + lane7) * 80 +
                              ((lane >> 3) & 1) * 16);
    const uint wA = (uint)((wid >> 1) * 11520 + (wid & 1) * 4320);

    const int CLS_NT[8] = {27, 18, 18, 12, 18, 12, 12, 8};
    float regAll[4] = {-3.4e38f, -3.4e38f, -3.4e38f, -3.4e38f};
    int t = 0;

    #pragma unroll 1
    for (int cls = 0; cls < 8; cls++) {
        float C[3][8][4];
        #pragma unroll
        for (int mt = 0; mt < 3; mt++)
            #pragma unroll
            for (int nt = 0; nt < 8; nt++)
                #pragma unroll
                for (int e = 0; e < 4; e++)
                    C[mt][nt][e] = 0.0f;

        const int ntap = CLS_NT[cls];
        #pragma unroll 1
        for (int j = 0; j < ntap; j++, t++) {
            cp_wait1();        // group carrying tap t retired
            __syncthreads();   // publish tap t; retire reads of slot (t+2)&3

            // prefetch tap t+2 into slot (t+2)&3 (commit EVERY iteration)
            if (t + 2 < 125) {
                const __half* src = g_wtH + tl_tap[t + 2] * 2048;
                char* dst = btb + ((t + 2) & 3) * 5120;
                for (int q = tid; q < 256; q += THREADS)
                    cpa16(dst + (q >> 2) * 80 + (q & 3) * 16,
                          src + (q >> 2) * 32 + (q & 3) * 8);
            }
            cp_commit();

            const uint bt_u = bt_u0 + (uint)((t & 3) * 5120) + laneB;
            const uint aa = xs_u + (uint)tl_abase[t] + wA + laneA;
            #pragma unroll
            for (int ks = 0; ks < 2; ks++) {
                uint bfr[8][2];
                #pragma unroll
                for (int q = 0; q < 4; q++) {
                    uint r[4];
                    ldm_x4(r, bt_u + (uint)(q * 1280 + ks * 32));
                    bfr[2 * q][0] = r[0];  bfr[2 * q][1] = r[1];
                    bfr[2 * q + 1][0] = r[2]; bfr[2 * q + 1][1] = r[3];
                }
                #pragma unroll
                for (int mt = 0; mt < 3; mt++) {
                    uint a[4];
                    ldm_x4(a, aa + (uint)(mt * 1440 + ks * 32));
                    #pragma unroll
                    for (int nt = 0; nt < 8; nt++)
                        mma_f16(C[mt][nt], a, bfr[nt]);
                }
            }
        }

        // ---- class epilogue: 3 stages by ri ----
        #pragma unroll 1
        for (int s = 0; s < 3; s++) {
            __syncthreads();
            if ((wid >> 1) == s) {
                const int rb = 3 * (wid & 1);
                #pragma unroll
                for (int mt = 0; mt < 3; mt++)
                    #pragma unroll
                    for (int nt = 0; nt < 8; nt++) {
                        int oc0 = nt * 8 + 2 * lm4;
                        int pos0 = (rb + mt) * 16 + ld4;
                        part[oc0 * PS + pos0]           = C[mt][nt][0];
                        part[(oc0 + 1) * PS + pos0]     = C[mt][nt][1];
                        part[oc0 * PS + pos0 + 8]       = C[mt][nt][2];
                        part[(oc0 + 1) * PS + pos0 + 8] = C[mt][nt][3];
                    }
            }
            __syncthreads();
            {
                const int oc = tid & 63, slot = tid >> 6;
                const float* pr = part + oc * PS;
                #pragma unroll
                for (int k = 0; k < 4; k++) {
                    int cc = slot + 3 * k;
                    if (cc < 10) {
                        int ch = (cc >= 5) ? 1 : 0;
                        int cw = cc - 5 * ch;
                        const float* pb = pr + ch * 48 + 3 * cw;
                        float m = regAll[k];
                        #pragma unroll
                        for (int u = 0; u < 3; u++)
                            #pragma unroll
                            for (int v = 0; v < 3; v++)
                                m = fmaxf(m, pb[u * 16 + v]);
                        regAll[k] = m;
                    }
                }
            }
        }
    }

    // ---- final: +bias, sum over oc per cell ----
    __syncthreads();
    float* red = part;    // [10][64]
    {
        const int oc = tid & 63, slot = tid >> 6;
        #pragma unroll
        for (int k = 0; k < 4; k++) {
            int cc = slot + 3 * k;
            if (cc < 10) red[cc * 64 + oc] = regAll[k] + bias[oc];
        }
    }
    __syncthreads();
    for (int cc = wid; cc < 10; cc += 6) {
        float v = red[cc * 64 + lane] + red[cc * 64 + 32 + lane];
        #pragma unroll
        for (int off = 16; off > 0; off >>= 1)
            v += __shfl_xor_sync(0xffffffffu, v, off);
        if (lane == 0) {
            int ch = (cc >= 5) ? 1 : 0;
            int cw = cc - 5 * ch;
            out[((b * 5 + odp) * 10 + 2 * ohp + ch) * 10 + 5 * whp + cw] = v;
        }
    }
}

// ---------------------------------------------------------------------------
extern "C" void kernel_launch(void* const* d_in, const int* in_sizes, int n_in,
                              void* d_out, int out_size) {
    const float* x    = (const float*)d_in[0];   // [16,32,16,32,32]
    const float* w    = (const float*)d_in[1];   // [32,64,5,5,5]
    const float* bias = (const float*)d_in[2];   // [64]
    float* out = (float*)d_out;                  // 8000

    wt_prep_kernel<<<(125 * 64 * 32 + 255) / 256, 256>>>(w);

    cudaFuncSetAttribute(fused_kernel,
                         cudaFuncAttributeMaxDynamicSharedMemorySize,
                         SMEM_BYTES);
    dim3 grid(2, 25, 16);   // (w half-line, odp*5+ohp, b)
    fused_kernel<<<grid, THREADS, SMEM_BYTES>>>(x, bias, out);
}

// round 16
// speedup vs baseline: 1.3097x; 1.1204x over previous
#include <cuda_runtime.h>
#include <cuda_fp16.h>
#include <cstdint>

// ============================================================================
// Fused ConvTranspose3d(32->64,k=5,s=2,p=2) + MaxPool(2)+MaxPool(3) + ch-sum
// via mma.sync FP16 implicit GEMM (m16n8k16, fp32 accum), ldmatrix loads.
//
// R16 = R15 resubmit after infra failure. Decoupled per-slot mbarrier
// pipeline: 4-slot B ring; full[s] (count=192, armed via
// cp.async.mbarrier.arrive.NOINC per thread — the default incrementing form
// deadlocks) and empty[s] (count=6, one arrive per warp). No __syncthreads
// in the tap loop -> warps slide up to ~2 taps apart and cover each other's
// latency. Block-wide convergence only at the 8 class epilogues.
//
// CTA = 1 od x 2 oh x 5 ow cells (grid 2x25x16 = 800, 192 thr, 6 warps,
// 2 CTAs/SM). Per parity class: GEMM M=288 (ri3 x rhi6 x j16, j innermost
// -> ldmatrix reads 8 consecutive 80B rows: conflict-free), N=64, K=32/tap.
// Epilogue per class: 3 stages by ri -> part[oc][PS=101] -> cell max.
// ============================================================================

typedef unsigned int uint;

#define THREADS 192
#define PS 101
// smem byte offsets
#define B_OFF    57600           // xs: 720 rows x 80B
#define PART_OFF 78080           // B ring: 4 x 5120B = 20480
#define TL_OFF   103936          // part: 64*101*4 = 25856B
#define MB_OFF   104944          // tl tables: 1000B; mbarriers: 8 x 8B
#define SMEM_BYTES 105024

__device__ __align__(16) __half g_wtH[125 * 64 * 32];   // [tap][oc][ic32]

// g_wtH[tap][oc][ic] <- fp16(w[ic][oc][kd][kh][kw])
__global__ void wt_prep_kernel(const float* __restrict__ w) {
    int idx = blockIdx.x * blockDim.x + threadIdx.x;
    if (idx >= 125 * 64 * 32) return;
    int ic  = idx & 31;
    int oc  = (idx >> 5) & 63;
    int tap = idx >> 11;
    g_wtH[(tap * 64 + oc) * 32 + ic] =
        __float2half_rn(w[(ic * 64 + oc) * 125 + tap]);
}

__device__ __forceinline__ void cpa16(char* s, const void* g) {
    uint sa = (uint)__cvta_generic_to_shared(s);
    asm volatile("cp.async.cg.shared.global [%0], [%1], 16;" :: "r"(sa), "l"(g));
}
__device__ __forceinline__ void mbar_init(uint a, uint cnt) {
    asm volatile("mbarrier.init.shared.b64 [%0], %1;"
                 :: "r"(a), "r"(cnt) : "memory");
}
__device__ __forceinline__ void mbar_arrive(uint a) {
    asm volatile("mbarrier.arrive.shared.b64 _, [%0];" :: "r"(a) : "memory");
}
__device__ __forceinline__ void cpasync_mbar_arrive_noinc(uint a) {
    asm volatile("cp.async.mbarrier.arrive.noinc.shared.b64 [%0];"
                 :: "r"(a) : "memory");
}
__device__ __forceinline__ void mbar_wait(uint a, uint par) {
    asm volatile("{\n\t.reg .pred P;\n\t"
                 "LW_%=:\n\t"
                 "mbarrier.try_wait.parity.shared.b64 P, [%0], %1;\n\t"
                 "@P bra.uni LD_%=;\n\t"
                 "bra.uni LW_%=;\n\t"
                 "LD_%=:\n\t}" :: "r"(a), "r"(par) : "memory");
}

__device__ __forceinline__ void ldm_x4(uint* r, uint addr) {
    asm volatile("ldmatrix.sync.aligned.m8n8.x4.shared.b16 {%0,%1,%2,%3}, [%4];"
                 : "=r"(r[0]), "=r"(r[1]), "=r"(r[2]), "=r"(r[3]) : "r"(addr));
}

__device__ __forceinline__ void mma_f16(float* c, const uint* a, const uint* b) {
    asm volatile(
        "mma.sync.aligned.m16n8k16.row.col.f32.f16.f16.f32 "
        "{%0,%1,%2,%3}, {%4,%5,%6,%7}, {%8,%9}, {%0,%1,%2,%3};"
        : "+f"(c[0]), "+f"(c[1]), "+f"(c[2]), "+f"(c[3])
        : "r"(a[0]), "r"(a[1]), "r"(a[2]), "r"(a[3]), "r"(b[0]), "r"(b[1]));
}

extern __shared__ char smem_raw[];

__global__ void __launch_bounds__(THREADS, 2)
fused_kernel(const float* __restrict__ x,
             const float* __restrict__ bias,
             float* __restrict__ out) {
    char*  xsb  = smem_raw;                     // x rows: R in [0,720), 80B
    char*  btb  = smem_raw + B_OFF;             // 4-slot B ring
    float* part = (float*)(smem_raw + PART_OFF);
    int* tl_tap   = (int*)(smem_raw + TL_OFF);
    int* tl_abase = tl_tap + 125;

    const int whp = blockIdx.x;                 // w half-line (5 ow cells)
    const int odp = blockIdx.y / 5;
    const int ohp = blockIdx.y % 5;
    const int b   = blockIdx.z;
    const int tid  = threadIdx.x;
    const int wid  = tid >> 5;
    const int lane = tid & 31;
    const int lane7 = lane & 7;
    const int lm4 = lane & 3, ld4 = lane >> 2;

    const uint xs_u  = (uint)__cvta_generic_to_shared(xsb);
    const uint bt_u0 = (uint)__cvta_generic_to_shared(btb);
    const uint mb_u  = (uint)__cvta_generic_to_shared(smem_raw + MB_OFF);
    // full[s] = mb_u + s*8 ; empty[s] = mb_u + 32 + s*8

    // ---- tap tables + mbarrier init (thread 0) ----
    if (tid == 0) {
        int t = 0;
        for (int pd = 0; pd < 2; pd++)
            for (int ph = 0; ph < 2; ph++)
                for (int pw = 0; pw < 2; pw++)
                    for (int jd = 0; jd < 3 - pd; jd++)
                        for (int jh = 0; jh < 3 - ph; jh++)
                            for (int jw = 0; jw < 3 - pw; jw++) {
                                int kd = pd + 2 * jd, kh = ph + 2 * jh,
                                    kw = pw + 2 * jw;
                                tl_tap[t] = (kd * 5 + kh) * 5 + kw;
                                tl_abase[t] =
                                    ((2 - jd) * 144 + (2 - jh) * 18 +
                                     (2 - jw)) * 80;
                                t++;
                            }
        #pragma unroll
        for (int s = 0; s < 4; s++) {
            mbar_init(mb_u + s * 8, THREADS);    // full
            mbar_init(mb_u + 32 + s * 8, 6);     // empty
        }
    }
    __syncthreads();    // tables + mbarriers visible

    // ---- prologue: fill slots 0 and 1, arm full[0], full[1] ----
    #pragma unroll
    for (int pf = 0; pf < 2; pf++) {
        const __half* src = g_wtH + tl_tap[pf] * 2048;
        char* dst = btb + pf * 5120;
        for (int q = tid; q < 256; q += THREADS)
            cpa16(dst + (q >> 2) * 80 + (q & 3) * 16,
                  src + (q >> 2) * 32 + (q & 3) * 8);
        cpasync_mbar_arrive_noinc(mb_u + pf * 8);
    }

    // ---- x patch fill: row R = (ild*8 + ilh)*18 + ilw, 32 ic halfs ----
    {
        const int d0 = 3 * odp - 1, h0 = 6 * ohp - 1, w0 = 15 * whp - 1;
        const float* xb0 = x + (size_t)b * 32 * 16384;
        for (int R = tid; R < 720; R += THREADS) {
            int ild = R / 144, rem = R % 144;
            int ilh = rem / 18, ilw = rem % 18;
            int id = d0 + ild, ih = h0 + ilh, iw = w0 + ilw;
            char* dst = xsb + R * 80;
            if (id >= 0 && ih >= 0 && iw >= 0) {
                const float* p = xb0 + (id * 32 + ih) * 32 + iw;
                #pragma unroll 4
                for (int icp = 0; icp < 16; icp++) {
                    float v0 = p[icp * 32768];
                    float v1 = p[icp * 32768 + 16384];
                    *(__half2*)(dst + icp * 4) = __floats2half2_rn(v0, v1);
                }
            } else {
                #pragma unroll
                for (int g2 = 0; g2 < 4; g2++)
                    *(uint4*)(dst + g2 * 16) = make_uint4(0, 0, 0, 0);
            }
        }
    }
    __syncthreads();    // xs visible to all warps

    // ---- per-lane / per-warp address constants ----
    const uint laneA = (uint)(lane7 * 80 + ((lane >> 3) & 1) * 640 +
                              (lane >> 4) * 16);
    const uint laneB = (uint)(((lane >> 4) * 8 + lane7) * 80 +
                              ((lane >> 3) & 1) * 16);
    const uint wA = (uint)((wid >> 1) * 11520 + (wid & 1) * 4320);

    const int CLS_NT[8] = {27, 18, 18, 12, 18, 12, 12, 8};
    float regAll[4] = {-3.4e38f, -3.4e38f, -3.4e38f, -3.4e38f};
    int t = 0;

    #pragma unroll 1
    for (int cls = 0; cls < 8; cls++) {
        float C[3][8][4];
        #pragma unroll
        for (int mt = 0; mt < 3; mt++)
            #pragma unroll
            for (int nt = 0; nt < 8; nt++)
                #pragma unroll
                for (int e = 0; e < 4; e++)
                    C[mt][nt][e] = 0.0f;

        const int ntap = CLS_NT[cls];
        #pragma unroll 1
        for (int j = 0; j < ntap; j++, t++) {
            // ---- producer: stage tap t+2 into slot (t+2)&3 ----
            if (t + 2 < 125) {
                const int tp = t + 2;
                const int s2 = tp & 3;
                if (tp >= 4)
                    mbar_wait(mb_u + 32 + s2 * 8,
                              (uint)(((tp >> 2) - 1) & 1));
                const __half* src = g_wtH + tl_tap[tp] * 2048;
                char* dst = btb + s2 * 5120;
                for (int q = tid; q < 256; q += THREADS)
                    cpa16(dst + (q >> 2) * 80 + (q & 3) * 16,
                          src + (q >> 2) * 32 + (q & 3) * 8);
                cpasync_mbar_arrive_noinc(mb_u + s2 * 8);
            }

            // ---- consumer: wait tap t's B tile ----
            mbar_wait(mb_u + (t & 3) * 8, (uint)((t >> 2) & 1));

            const uint bt_u = bt_u0 + (uint)((t & 3) * 5120) + laneB;
            const uint aa = xs_u + (uint)tl_abase[t] + wA + laneA;
            #pragma unroll
            for (int ks = 0; ks < 2; ks++) {
                uint bfr[8][2];
                #pragma unroll
                for (int q = 0; q < 4; q++) {
                    uint r[4];
                    ldm_x4(r, bt_u + (uint)(q * 1280 + ks * 32));
                    bfr[2 * q][0] = r[0];  bfr[2 * q][1] = r[1];
                    bfr[2 * q + 1][0] = r[2]; bfr[2 * q + 1][1] = r[3];
                }
                #pragma unroll
                for (int mt = 0; mt < 3; mt++) {
                    uint a[4];
                    ldm_x4(a, aa + (uint)(mt * 1440 + ks * 32));
                    #pragma unroll
                    for (int nt = 0; nt < 8; nt++)
                        mma_f16(C[mt][nt], a, bfr[nt]);
                }
            }

            __syncwarp();
            if (lane == 0) mbar_arrive(mb_u + 32 + (t & 3) * 8);
        }

        // ---- class epilogue: 3 stages by ri (block-converging) ----
        #pragma unroll 1
        for (int s = 0; s < 3; s++) {
            __syncthreads();
            if ((wid >> 1) == s) {
                const int rb = 3 * (wid & 1);
                #pragma unroll
                for (int mt = 0; mt < 3; mt++)
                    #pragma unroll
                    for (int nt = 0; nt < 8; nt++) {
                        int oc0 = nt * 8 + 2 * lm4;
                        int pos0 = (rb + mt) * 16 + ld4;
                        part[oc0 * PS + pos0]           = C[mt][nt][0];
                        part[(oc0 + 1) * PS + pos0]     = C[mt][nt][1];
                        part[oc0 * PS + pos0 + 8]       = C[mt][nt][2];
                        part[(oc0 + 1) * PS + pos0 + 8] = C[mt][nt][3];
                    }
            }
            __syncthreads();
            {
                const int oc = tid & 63, slot = tid >> 6;
                const float* pr = part + oc * PS;
                #pragma unroll
                for (int k = 0; k < 4; k++) {
                    int cc = slot + 3 * k;
                    if (cc < 10) {
                        int ch = (cc >= 5) ? 1 : 0;
                        int cw = cc - 5 * ch;
                        const float* pb = pr + ch * 48 + 3 * cw;
                        float m = regAll[k];
                        #pragma unroll
                        for (int u = 0; u < 3; u++)
                            #pragma unroll
                            for (int v = 0; v < 3; v++)
                                m = fmaxf(m, pb[u * 16 + v]);
                        regAll[k] = m;
                    }
                }
            }
        }
    }

    // ---- final: +bias, sum over oc per cell ----
    __syncthreads();
    float* red = part;    // [10][64]
    {
        const int oc = tid & 63, slot = tid >> 6;
        #pragma unroll
        for (int k = 0; k < 4; k++) {
            int cc = slot + 3 * k;
            if (cc < 10) red[cc * 64 + oc] = regAll[k] + bias[oc];
        }
    }
    __syncthreads();
    for (int cc = wid; cc < 10; cc += 6) {
        float v = red[cc * 64 + lane] + red[cc * 64 + 32 + lane];
        #pragma unroll
        for (int off = 16; off > 0; off >>= 1)
            v += __shfl_xor_sync(0xffffffffu, v, off);
        if (lane == 0) {
            int ch = (cc >= 5) ? 1 : 0;
            int cw = cc - 5 * ch;
            out[((b * 5 + odp) * 10 + 2 * ohp + ch) * 10 + 5 * whp + cw] = v;
        }
    }
}

// ---------------------------------------------------------------------------
extern "C" void kernel_launch(void* const* d_in, const int* in_sizes, int n_in,
                              void* d_out, int out_size) {
    const float* x    = (const float*)d_in[0];   // [16,32,16,32,32]
    const float* w    = (const float*)d_in[1];   // [32,64,5,5,5]
    const float* bias = (const float*)d_in[2];   // [64]
    float* out = (float*)d_out;                  // 8000

    wt_prep_kernel<<<(125 * 64 * 32 + 255) / 256, 256>>>(w);

    cudaFuncSetAttribute(fused_kernel,
                         cudaFuncAttributeMaxDynamicSharedMemorySize,
                         SMEM_BYTES);
    dim3 grid(2, 25, 16);   // (w half-line, odp*5+ohp, b)
    fused_kernel<<<grid, THREADS, SMEM_BYTES>>>(x, bias, out);
}

// round 17
// speedup vs baseline: 1.3725x; 1.0480x over previous
#include <cuda_runtime.h>
#include <cuda_fp16.h>
#include <cstdint>

// ============================================================================
// Fused ConvTranspose3d(32->64,k=5,s=2,p=2) + MaxPool(2)+MaxPool(3) + ch-sum
// via mma.sync FP16 implicit GEMM (m16n8k16, fp32 accum), ldmatrix loads.
//
// R17 = R16 pipeline + WARP-LOCAL class epilogue:
// A warp's C tile holds complete cells (its 3 mt = within-cell h positions,
// j = w positions), so per class each warp privately reduces C -> 5 cells x
// 64 oc via a per-warp 4KB smem strip (XOR-swizzled, conflict-free, only
// __syncwarp) and accumulates into regAll[10] registers. Block-wide sync
// drops from 48 barriers to ONE final combine (max over ri warps + bias +
// oc-sum). Tap loop / mbarrier pipeline identical to R16 (4-slot ring,
// cp.async.mbarrier.arrive.noinc full[s], per-warp empty[s]).
//
// CTA = 1 od x 2 oh x 5 ow cells (grid 2x25x16 = 800, 192 thr, 6 warps,
// 2 CTAs/SM). Per parity class: GEMM M=288 (ri3 x rhi6 x j16, j innermost
// -> ldmatrix reads 8 consecutive 80B rows: conflict-free), N=64, K=32/tap.
// ============================================================================

typedef unsigned int uint;

#define THREADS 192
// smem byte offsets
#define B_OFF     57600          // xs: 720 rows x 80B
#define STRIP_OFF 78080          // B ring: 4 x 5120B = 20480
#define TL_OFF    102656         // strips: 6 x 4096B = 24576
#define MB_OFF    103656         // tl tables: 1000B; mbarriers 64B
#define SMEM_BYTES 103744

__device__ __align__(16) __half g_wtH[125 * 64 * 32];   // [tap][oc][ic32]

// g_wtH[tap][oc][ic] <- fp16(w[ic][oc][kd][kh][kw])
__global__ void wt_prep_kernel(const float* __restrict__ w) {
    int idx = blockIdx.x * blockDim.x + threadIdx.x;
    if (idx >= 125 * 64 * 32) return;
    int ic  = idx & 31;
    int oc  = (idx >> 5) & 63;
    int tap = idx >> 11;
    g_wtH[(tap * 64 + oc) * 32 + ic] =
        __float2half_rn(w[(ic * 64 + oc) * 125 + tap]);
}

__device__ __forceinline__ void cpa16(char* s, const void* g) {
    uint sa = (uint)__cvta_generic_to_shared(s);
    asm volatile("cp.async.cg.shared.global [%0], [%1], 16;" :: "r"(sa), "l"(g));
}
__device__ __forceinline__ void mbar_init(uint a, uint cnt) {
    asm volatile("mbarrier.init.shared.b64 [%0], %1;"
                 :: "r"(a), "r"(cnt) : "memory");
}
__device__ __forceinline__ void mbar_arrive(uint a) {
    asm volatile("mbarrier.arrive.shared.b64 _, [%0];" :: "r"(a) : "memory");
}
__device__ __forceinline__ void cpasync_mbar_arrive_noinc(uint a) {
    asm volatile("cp.async.mbarrier.arrive.noinc.shared.b64 [%0];"
                 :: "r"(a) : "memory");
}
__device__ __forceinline__ void mbar_wait(uint a, uint par) {
    asm volatile("{\n\t.reg .pred P;\n\t"
                 "LW_%=:\n\t"
                 "mbarrier.try_wait.parity.shared.b64 P, [%0], %1;\n\t"
                 "@P bra.uni LD_%=;\n\t"
                 "bra.uni LW_%=;\n\t"
                 "LD_%=:\n\t}" :: "r"(a), "r"(par) : "memory");
}

__device__ __forceinline__ void ldm_x4(uint* r, uint addr) {
    asm volatile("ldmatrix.sync.aligned.m8n8.x4.shared.b16 {%0,%1,%2,%3}, [%4];"
                 : "=r"(r[0]), "=r"(r[1]), "=r"(r[2]), "=r"(r[3]) : "r"(addr));
}

__device__ __forceinline__ void mma_f16(float* c, const uint* a, const uint* b) {
    asm volatile(
        "mma.sync.aligned.m16n8k16.row.col.f32.f16.f16.f32 "
        "{%0,%1,%2,%3}, {%4,%5,%6,%7}, {%8,%9}, {%0,%1,%2,%3};"
        : "+f"(c[0]), "+f"(c[1]), "+f"(c[2]), "+f"(c[3])
        : "r"(a[0]), "r"(a[1]), "r"(a[2]), "r"(a[3]), "r"(b[0]), "r"(b[1]));
}

extern __shared__ char smem_raw[];

__global__ void __launch_bounds__(THREADS, 2)
fused_kernel(const float* __restrict__ x,
             const float* __restrict__ bias,
             float* __restrict__ out) {
    char*  xsb  = smem_raw;                     // x rows: R in [0,720), 80B
    char*  btb  = smem_raw + B_OFF;             // 4-slot B ring
    int* tl_tap   = (int*)(smem_raw + TL_OFF);
    int* tl_abase = tl_tap + 125;

    const int whp = blockIdx.x;                 // w half-line (5 ow cells)
    const int odp = blockIdx.y / 5;
    const int ohp = blockIdx.y % 5;
    const int b   = blockIdx.z;
    const int tid  = threadIdx.x;
    const int wid  = tid >> 5;
    const int lane = tid & 31;
    const int lane7 = lane & 7;
    const int lm4 = lane & 3, ld4 = lane >> 2;

    const uint xs_u  = (uint)__cvta_generic_to_shared(xsb);
    const uint bt_u0 = (uint)__cvta_generic_to_shared(btb);
    const uint mb_u  = (uint)__cvta_generic_to_shared(smem_raw + MB_OFF);
    // full[s] = mb_u + s*8 ; empty[s] = mb_u + 32 + s*8

    // ---- tap tables + mbarrier init (thread 0) ----
    if (tid == 0) {
        int t = 0;
        for (int pd = 0; pd < 2; pd++)
            for (int ph = 0; ph < 2; ph++)
                for (int pw = 0; pw < 2; pw++)
                    for (int jd = 0; jd < 3 - pd; jd++)
                        for (int jh = 0; jh < 3 - ph; jh++)
                            for (int jw = 0; jw < 3 - pw; jw++) {
                                int kd = pd + 2 * jd, kh = ph + 2 * jh,
                                    kw = pw + 2 * jw;
                                tl_tap[t] = (kd * 5 + kh) * 5 + kw;
                                tl_abase[t] =
                                    ((2 - jd) * 144 + (2 - jh) * 18 +
                                     (2 - jw)) * 80;
                                t++;
                            }
        #pragma unroll
        for (int s = 0; s < 4; s++) {
            mbar_init(mb_u + s * 8, THREADS);    // full
            mbar_init(mb_u + 32 + s * 8, 6);     // empty
        }
    }
    __syncthreads();    // tables + mbarriers visible

    // ---- prologue: fill slots 0 and 1, arm full[0], full[1] ----
    #pragma unroll
    for (int pf = 0; pf < 2; pf++) {
        const __half* src = g_wtH + tl_tap[pf] * 2048;
        char* dst = btb + pf * 5120;
        for (int q = tid; q < 256; q += THREADS)
            cpa16(dst + (q >> 2) * 80 + (q & 3) * 16,
                  src + (q >> 2) * 32 + (q & 3) * 8);
        cpasync_mbar_arrive_noinc(mb_u + pf * 8);
    }

    // ---- x patch fill: row R = (ild*8 + ilh)*18 + ilw, 32 ic halfs ----
    {
        const int d0 = 3 * odp - 1, h0 = 6 * ohp - 1, w0 = 15 * whp - 1;
        const float* xb0 = x + (size_t)b * 32 * 16384;
        for (int R = tid; R < 720; R += THREADS) {
            int ild = R / 144, rem = R % 144;
            int ilh = rem / 18, ilw = rem % 18;
            int id = d0 + ild, ih = h0 + ilh, iw = w0 + ilw;
            char* dst = xsb + R * 80;
            if (id >= 0 && ih >= 0 && iw >= 0) {
                const float* p = xb0 + (id * 32 + ih) * 32 + iw;
                #pragma unroll 4
                for (int icp = 0; icp < 16; icp++) {
                    float v0 = p[icp * 32768];
                    float v1 = p[icp * 32768 + 16384];
                    *(__half2*)(dst + icp * 4) = __floats2half2_rn(v0, v1);
                }
            } else {
                #pragma unroll
                for (int g2 = 0; g2 < 4; g2++)
                    *(uint4*)(dst + g2 * 16) = make_uint4(0, 0, 0, 0);
            }
        }
    }
    __syncthreads();    // xs visible to all warps

    // ---- per-lane / per-warp address constants ----
    const uint laneA = (uint)(lane7 * 80 + ((lane >> 3) & 1) * 640 +
                              (lane >> 4) * 16);
    const uint laneB = (uint)(((lane >> 4) * 8 + lane7) * 80 +
                              ((lane >> 3) & 1) * 16);
    const uint wA = (uint)((wid >> 1) * 11520 + (wid & 1) * 4320);
    char* strip = smem_raw + STRIP_OFF + wid * 4096;   // per-warp scratch

    const int CLS_NT[8] = {27, 18, 18, 12, 18, 12, 12, 8};
    float regAll[10];
    #pragma unroll
    for (int k = 0; k < 10; k++) regAll[k] = -3.4e38f;
    int t = 0;

    #pragma unroll 1
    for (int cls = 0; cls < 8; cls++) {
        float C[3][8][4];
        #pragma unroll
        for (int mt = 0; mt < 3; mt++)
            #pragma unroll
            for (int nt = 0; nt < 8; nt++)
                #pragma unroll
                for (int e = 0; e < 4; e++)
                    C[mt][nt][e] = 0.0f;

        const int ntap = CLS_NT[cls];
        #pragma unroll 1
        for (int j = 0; j < ntap; j++, t++) {
            // ---- producer: stage tap t+2 into slot (t+2)&3 ----
            if (t + 2 < 125) {
                const int tp = t + 2;
                const int s2 = tp & 3;
                if (tp >= 4)
                    mbar_wait(mb_u + 32 + s2 * 8,
                              (uint)(((tp >> 2) - 1) & 1));
                const __half* src = g_wtH + tl_tap[tp] * 2048;
                char* dst = btb + s2 * 5120;
                for (int q = tid; q < 256; q += THREADS)
                    cpa16(dst + (q >> 2) * 80 + (q & 3) * 16,
                          src + (q >> 2) * 32 + (q & 3) * 8);
                cpasync_mbar_arrive_noinc(mb_u + s2 * 8);
            }

            // ---- consumer: wait tap t's B tile ----
            mbar_wait(mb_u + (t & 3) * 8, (uint)((t >> 2) & 1));

            const uint bt_u = bt_u0 + (uint)((t & 3) * 5120) + laneB;
            const uint aa = xs_u + (uint)tl_abase[t] + wA + laneA;
            #pragma unroll
            for (int ks = 0; ks < 2; ks++) {
                uint bfr[8][2];
                #pragma unroll
                for (int q = 0; q < 4; q++) {
                    uint r[4];
                    ldm_x4(r, bt_u + (uint)(q * 1280 + ks * 32));
                    bfr[2 * q][0] = r[0];  bfr[2 * q][1] = r[1];
                    bfr[2 * q + 1][0] = r[2]; bfr[2 * q + 1][1] = r[3];
                }
                #pragma unroll
                for (int mt = 0; mt < 3; mt++) {
                    uint a[4];
                    ldm_x4(a, aa + (uint)(mt * 1440 + ks * 32));
                    #pragma unroll
                    for (int nt = 0; nt < 8; nt++)
                        mma_f16(C[mt][nt], a, bfr[nt]);
                }
            }

            __syncwarp();
            if (lane == 0) mbar_arrive(mb_u + 32 + (t & 3) * 8);
        }

        // ---- class epilogue: WARP-LOCAL (no block barriers) ----
        // strip[j][oc^( (j&7)<<3 )], j = w index 0..15, 256B row stride.
        {
            const uint swz = (uint)(ld4 << 3);   // (j&7)<<3 for j=ld4, ld4+8
            #pragma unroll
            for (int nt = 0; nt < 8; nt++) {
                // mt = within-cell h position -> max over mt is per-cell
                float lo0 = fmaxf(fmaxf(C[0][nt][0], C[1][nt][0]), C[2][nt][0]);
                float lo1 = fmaxf(fmaxf(C[0][nt][1], C[1][nt][1]), C[2][nt][1]);
                float hi0 = fmaxf(fmaxf(C[0][nt][2], C[1][nt][2]), C[2][nt][2]);
                float hi1 = fmaxf(fmaxf(C[0][nt][3], C[1][nt][3]), C[2][nt][3]);
                uint col = (uint)(nt * 8 + 2 * lm4) ^ swz;   // even, ^swz keeps bit0
                *(float2*)(strip + ld4 * 256 + col * 4) = make_float2(lo0, lo1);
                *(float2*)(strip + (ld4 + 8) * 256 + col * 4) =
                    make_float2(hi0, hi1);
            }
            __syncwarp();
            #pragma unroll
            for (int k = 0; k < 10; k++) {
                const int cw = k >> 1;
                const int ocr = ((k & 1) << 5) + lane;
                float m = regAll[k];
                #pragma unroll
                for (int dj = 0; dj < 3; dj++) {
                    int jj = 3 * cw + dj;                    // <= 14 (j=15 junk)
                    uint cidx = (uint)ocr ^ (uint)((jj & 7) << 3);
                    m = fmaxf(m, *(const float*)(strip + jj * 256 + cidx * 4));
                }
                regAll[k] = m;
            }
            __syncwarp();   // strip reusable next class (warp-private)
        }
    }

    // ---- final combine (single block-converging phase) ----
    __syncthreads();                 // all warps done; strips free for reuse
    float* red  = (float*)(smem_raw + STRIP_OFF);          // [6][10][32]
    float* red2 = (float*)(smem_raw + STRIP_OFF + 8192);   // [10][64]
    #pragma unroll
    for (int k = 0; k < 10; k++)
        red[wid * 320 + k * 32 + lane] = regAll[k];
    __syncthreads();
    {
        const int oc = tid & 63, s3 = tid >> 6;
        #pragma unroll
        for (int m2 = 0; m2 < 4; m2++) {
            int cc = s3 + 3 * m2;
            if (cc < 10) {
                int ch = cc / 5, cw = cc % 5;
                int k = cw * 2 + (oc >> 5);
                int l = oc & 31;
                float v =          red[(0 + ch) * 320 + k * 32 + l];
                v = fmaxf(v, red[(2 + ch) * 320 + k * 32 + l]);
                v = fmaxf(v, red[(4 + ch) * 320 + k * 32 + l]);
                red2[cc * 64 + oc] = v + bias[oc];
            }
        }
    }
    __syncthreads();
    for (int cc = wid; cc < 10; cc += 6) {
        float v = red2[cc * 64 + lane] + red2[cc * 64 + 32 + lane];
        #pragma unroll
        for (int off = 16; off > 0; off >>= 1)
            v += __shfl_xor_sync(0xffffffffu, v, off);
        if (lane == 0) {
            int ch = cc / 5, cw = cc % 5;
            out[((b * 5 + odp) * 10 + 2 * ohp + ch) * 10 + 5 * whp + cw] = v;
        }
    }
}

// ---------------------------------------------------------------------------
extern "C" void kernel_launch(void* const* d_in, const int* in_sizes, int n_in,
                              void* d_out, int out_size) {
    const float* x    = (const float*)d_in[0];   // [16,32,16,32,32]
    const float* w    = (const float*)d_in[1];   // [32,64,5,5,5]
    const float* bias = (const float*)d_in[2];   // [64]
    float* out = (float*)d_out;                  // 8000

    wt_prep_kernel<<<(125 * 64 * 32 + 255) / 256, 256>>>(w);

    cudaFuncSetAttribute(fused_kernel,
                         cudaFuncAttributeMaxDynamicSharedMemorySize,
                         SMEM_BYTES);
    dim3 grid(2, 25, 16);   // (w half-line, odp*5+ohp, b)
    fused_kernel<<<grid, THREADS, SMEM_BYTES>>>(x, bias, out);
}